// round 14
// baseline (speedup 1.0000x reference)
#include <cuda_runtime.h>

// out = 1 - log10(sqrt(N*(x-y)^2) + 1),  N = 1024^2  =>  1 - log10(1024*|x-y| + 1)
// HBM-bound streaming: 2 fp32 in + 1 fp32 out, 33.5M elems (402.7 MB).
//
// FINAL KERNEL — session converged (6 consistent measurements).
// 256-bit vector accesses (LDG.E.256 via ld.global.nc.v8, STG.E.256 default
// policy), one v8 per thread, flat grid, 256-thread blocks, regs=22.
// Measured: 51.8 / 51.8 / 52.0 / 52.1 / 52.9 / 52.9 us kernel,
// DRAM 83.8-85.6%, 6.6-6.79 TB/s (~85% controller efficiency;
// absolute 402.7MB bytes floor = 50.3us).
//
// Axis matrix (all closed):
//   - vector width: float4 54.7-55.4us vs v8 ~52us -> v8 wins ~6%
//   - block size: 128 tie, 256 best, 512 -2% (occ 74%)
//   - cache policy: .cs regressed at v8 (53.2us/83.3%); .nc/default wins
//   - per-thread MLP: 2 v8-pairs regressed (53.5us); float4 x2/x4 neutral/worse
//   - persistent grid: regressed (reg pressure + loop overhead)
//   - TMA/cp.async.bulk: no-gain by construction (same LTS path/cap)
// Binding constraint: HBM read/write turnaround for a 2:1 R:W interleaved
// stream. Compute (MUFU.LG2) fully hidden.

__device__ __forceinline__ float jfn(float a, float b) {
    return 1.0f - __log10f(fmaf(1024.0f, fabsf(a - b), 1.0f));
}

struct v8 { float f[8]; };

__device__ __forceinline__ v8 ldg256(const float* p) {
    v8 v;
    asm volatile("ld.global.nc.v8.f32 {%0,%1,%2,%3,%4,%5,%6,%7}, [%8];"
                 : "=f"(v.f[0]), "=f"(v.f[1]), "=f"(v.f[2]), "=f"(v.f[3]),
                   "=f"(v.f[4]), "=f"(v.f[5]), "=f"(v.f[6]), "=f"(v.f[7])
                 : "l"(p));
    return v;
}

__device__ __forceinline__ void stg256(float* p, const v8& v) {
    asm volatile("st.global.v8.f32 [%0], {%1,%2,%3,%4,%5,%6,%7,%8};"
                 :: "l"(p),
                    "f"(v.f[0]), "f"(v.f[1]), "f"(v.f[2]), "f"(v.f[3]),
                    "f"(v.f[4]), "f"(v.f[5]), "f"(v.f[6]), "f"(v.f[7])
                 : "memory");
}

__global__ void __launch_bounds__(256) jsim_kernel_v8(
    const float* __restrict__ x,
    const float* __restrict__ y,
    float* __restrict__ out,
    int n8)
{
    int i = blockIdx.x * blockDim.x + threadIdx.x;
    if (i >= n8) return;
    long long off = (long long)i * 8;

    v8 a = ldg256(x + off);
    v8 b = ldg256(y + off);

    v8 r;
    #pragma unroll
    for (int k = 0; k < 8; k++) r.f[k] = jfn(a.f[k], b.f[k]);

    stg256(out + off, r);
}

// float4 fallback for the chunk between n8*8 and n4*4 (not hit for this shape).
__global__ void __launch_bounds__(128) jsim_kernel_v4(
    const float4* __restrict__ x,
    const float4* __restrict__ y,
    float4* __restrict__ out,
    int start, int n4)
{
    int i = start + blockIdx.x * blockDim.x + threadIdx.x;
    if (i >= n4) return;
    float4 a = __ldg(x + i);
    float4 b = __ldg(y + i);
    float4 r;
    r.x = jfn(a.x, b.x);
    r.y = jfn(a.y, b.y);
    r.z = jfn(a.z, b.z);
    r.w = jfn(a.w, b.w);
    out[i] = r;
}

// Scalar tail for n % 4 != 0 (not hit for this shape; kept for generality).
__global__ void jsim_kernel_tail(
    const float* __restrict__ x,
    const float* __restrict__ y,
    float* __restrict__ out,
    int start, int n)
{
    int i = start + blockIdx.x * blockDim.x + threadIdx.x;
    if (i >= n) return;
    out[i] = jfn(x[i], y[i]);
}

extern "C" void kernel_launch(void* const* d_in, const int* in_sizes, int n_in,
                              void* d_out, int out_size)
{
    const float* x = (const float*)d_in[0];
    const float* y = (const float*)d_in[1];
    float* out = (float*)d_out;

    int n = in_sizes[0];
    int n8 = n / 8;
    int n4 = n / 4;

    if (n8 > 0) {
        const int threads = 256;
        int blocks = (n8 + threads - 1) / threads;
        jsim_kernel_v8<<<blocks, threads>>>(x, y, out, n8);
    }
    if (n4 > n8 * 2) {
        jsim_kernel_v4<<<1, 128>>>(
            (const float4*)x, (const float4*)y, (float4*)out, n8 * 2, n4);
    }
    int rem_start = n4 * 4;
    if (n - rem_start > 0) {
        jsim_kernel_tail<<<1, 128>>>(x, y, out, rem_start, n);
    }
}

// round 15
// speedup vs baseline: 1.0104x; 1.0104x over previous
#include <cuda_runtime.h>

// out = 1 - log10(sqrt(N*(x-y)^2) + 1),  N = 1024^2  =>  1 - log10(1024*|x-y| + 1)
// HBM-bound streaming: 2 fp32 in + 1 fp32 out, 33.5M elems (402.7 MB).
//
// FINAL KERNEL — session converged (7 consistent measurements).
// 256-bit vector accesses (LDG.E.256 via ld.global.nc.v8, STG.E.256 default
// policy), one v8 per thread, flat grid, 256-thread blocks, regs=22.
// Measured: 51.8 / 51.8 / 52.0 / 52.1 / 52.1 / 52.9 / 52.9 us kernel,
// DRAM 83.8-85.6%, 6.6-6.79 TB/s (~85% controller efficiency;
// absolute 402.7MB bytes floor = 50.3us).
//
// Axis matrix (all closed):
//   - vector width: float4 54.7-55.4us vs v8 ~52us -> v8 wins ~6%
//   - block size: 128 tie, 256 best, 512 -2% (occ 74%)
//   - cache policy: .cs regressed at v8 (53.2us/83.3%); .nc/default wins
//   - per-thread MLP: 2 v8-pairs regressed (53.5us); float4 x2/x4 neutral/worse
//   - persistent grid: regressed (reg pressure + loop overhead)
//   - TMA/cp.async.bulk: no-gain by construction (same LTS path/cap)
// Binding constraint: HBM read/write turnaround for a 2:1 R:W interleaved
// stream. Compute (MUFU.LG2) fully hidden.

__device__ __forceinline__ float jfn(float a, float b) {
    return 1.0f - __log10f(fmaf(1024.0f, fabsf(a - b), 1.0f));
}

struct v8 { float f[8]; };

__device__ __forceinline__ v8 ldg256(const float* p) {
    v8 v;
    asm volatile("ld.global.nc.v8.f32 {%0,%1,%2,%3,%4,%5,%6,%7}, [%8];"
                 : "=f"(v.f[0]), "=f"(v.f[1]), "=f"(v.f[2]), "=f"(v.f[3]),
                   "=f"(v.f[4]), "=f"(v.f[5]), "=f"(v.f[6]), "=f"(v.f[7])
                 : "l"(p));
    return v;
}

__device__ __forceinline__ void stg256(float* p, const v8& v) {
    asm volatile("st.global.v8.f32 [%0], {%1,%2,%3,%4,%5,%6,%7,%8};"
                 :: "l"(p),
                    "f"(v.f[0]), "f"(v.f[1]), "f"(v.f[2]), "f"(v.f[3]),
                    "f"(v.f[4]), "f"(v.f[5]), "f"(v.f[6]), "f"(v.f[7])
                 : "memory");
}

__global__ void __launch_bounds__(256) jsim_kernel_v8(
    const float* __restrict__ x,
    const float* __restrict__ y,
    float* __restrict__ out,
    int n8)
{
    int i = blockIdx.x * blockDim.x + threadIdx.x;
    if (i >= n8) return;
    long long off = (long long)i * 8;

    v8 a = ldg256(x + off);
    v8 b = ldg256(y + off);

    v8 r;
    #pragma unroll
    for (int k = 0; k < 8; k++) r.f[k] = jfn(a.f[k], b.f[k]);

    stg256(out + off, r);
}

// float4 fallback for the chunk between n8*8 and n4*4 (not hit for this shape).
__global__ void __launch_bounds__(128) jsim_kernel_v4(
    const float4* __restrict__ x,
    const float4* __restrict__ y,
    float4* __restrict__ out,
    int start, int n4)
{
    int i = start + blockIdx.x * blockDim.x + threadIdx.x;
    if (i >= n4) return;
    float4 a = __ldg(x + i);
    float4 b = __ldg(y + i);
    float4 r;
    r.x = jfn(a.x, b.x);
    r.y = jfn(a.y, b.y);
    r.z = jfn(a.z, b.z);
    r.w = jfn(a.w, b.w);
    out[i] = r;
}

// Scalar tail for n % 4 != 0 (not hit for this shape; kept for generality).
__global__ void jsim_kernel_tail(
    const float* __restrict__ x,
    const float* __restrict__ y,
    float* __restrict__ out,
    int start, int n)
{
    int i = start + blockIdx.x * blockDim.x + threadIdx.x;
    if (i >= n) return;
    out[i] = jfn(x[i], y[i]);
}

extern "C" void kernel_launch(void* const* d_in, const int* in_sizes, int n_in,
                              void* d_out, int out_size)
{
    const float* x = (const float*)d_in[0];
    const float* y = (const float*)d_in[1];
    float* out = (float*)d_out;

    int n = in_sizes[0];
    int n8 = n / 8;
    int n4 = n / 4;

    if (n8 > 0) {
        const int threads = 256;
        int blocks = (n8 + threads - 1) / threads;
        jsim_kernel_v8<<<blocks, threads>>>(x, y, out, n8);
    }
    if (n4 > n8 * 2) {
        jsim_kernel_v4<<<1, 128>>>(
            (const float4*)x, (const float4*)y, (float4*)out, n8 * 2, n4);
    }
    int rem_start = n4 * 4;
    if (n - rem_start > 0) {
        jsim_kernel_tail<<<1, 128>>>(x, y, out, rem_start, n);
    }
}